// round 1
// baseline (speedup 1.0000x reference)
#include <cuda_runtime.h>

// Fused sum-over-seq + concat:
//   out[b, i, d] = sum_l x_i[b, l, d]
// 8 inputs x_i : [512, L_i, 128] fp32, L_i in {64,128,...,512} (multiples of 64)
// out : [512, 8, 128] fp32
//
// Pure streaming reduction: ~604 MB read once -> HBM-bound.
// One CTA per (input, batch): rows read as 32x float4 (coalesced 512B/row),
// 4 warp-stripes over L with x4 unroll for MLP, smem cross-stripe reduce.

#define NUM_IN 8
#define BATCH 512
#define DVEC 32   // 128 floats = 32 float4 per row

struct Args {
    const float4* in[NUM_IN];
    int len[NUM_IN];
};

__global__ __launch_bounds__(128, 16)
void sum_cat_kernel(Args args, float4* __restrict__ out) {
    const int bid = blockIdx.x;
    const int i = (NUM_IN - 1) - (bid >> 9);   // longest sequences scheduled first
    const int b = bid & (BATCH - 1);
    const int L = args.len[i];

    const float4* __restrict__ base = args.in[i] + (size_t)b * (size_t)L * DVEC;

    const int c = threadIdx.x & 31;   // float4 column within the row
    const int s = threadIdx.x >> 5;   // warp stripe 0..3

    float4 acc = make_float4(0.f, 0.f, 0.f, 0.f);

    // L is a multiple of 64 -> divisible by 16: no remainder handling.
    for (int l = s; l < L; l += 16) {
        const float4 v0 = base[(size_t)(l     ) * DVEC + c];
        const float4 v1 = base[(size_t)(l +  4) * DVEC + c];
        const float4 v2 = base[(size_t)(l +  8) * DVEC + c];
        const float4 v3 = base[(size_t)(l + 12) * DVEC + c];
        acc.x += (v0.x + v1.x) + (v2.x + v3.x);
        acc.y += (v0.y + v1.y) + (v2.y + v3.y);
        acc.z += (v0.z + v1.z) + (v2.z + v3.z);
        acc.w += (v0.w + v1.w) + (v2.w + v3.w);
    }

    __shared__ float4 sm[4][DVEC];
    sm[s][c] = acc;
    __syncthreads();

    if (threadIdx.x < 32) {
        const float4 a0 = sm[0][c];
        const float4 a1 = sm[1][c];
        const float4 a2 = sm[2][c];
        const float4 a3 = sm[3][c];
        float4 r;
        r.x = (a0.x + a1.x) + (a2.x + a3.x);
        r.y = (a0.y + a1.y) + (a2.y + a3.y);
        r.z = (a0.z + a1.z) + (a2.z + a3.z);
        r.w = (a0.w + a1.w) + (a2.w + a3.w);
        // out[b, i, :] -> float4 index (b*8 + i)*32 + c
        out[((size_t)b * NUM_IN + i) * DVEC + c] = r;
    }
}

extern "C" void kernel_launch(void* const* d_in, const int* in_sizes, int n_in,
                              void* d_out, int out_size) {
    Args args;
    for (int i = 0; i < NUM_IN; ++i) {
        args.in[i]  = (const float4*)d_in[i];
        args.len[i] = in_sizes[i] / (BATCH * 128);   // elements / (B*D) = L_i
    }
    sum_cat_kernel<<<NUM_IN * BATCH, 128>>>(args, (float4*)d_out);
}